// round 1
// baseline (speedup 1.0000x reference)
#include <cuda_runtime.h>
#include <cuda_bf16.h>
#include <cstdint>

// Problem constants (B=1, S=8192, D=1024, Hq=16, Hk=4, hd=64, W=512)
#define S_LEN   8192
#define D_MODEL 1024
#define QKV_N   1536          // (16 + 2*4) * 64
#define HQ      16
#define HK      4
#define HD      64
#define WIN     512
#define NB      16            // S / WIN
#define KV_COL0 1024          // kv_cache = qkv columns [1024, 1536)
#define KV_LD   512

// -------- scratch (device globals: allocation-guard-safe) --------
__device__ float g_qkv[(size_t)S_LEN * QKV_N];   // [8192, 1536]
__device__ float g_att[(size_t)S_LEN * D_MODEL]; // [8192, 1024]

// ============================================================================
// NT GEMM: C[M,N] = A[M,K] * B[N,K]^T, all row-major, K-contiguous operands.
// 128x128 tile, BK=16, 256 threads, 8x8 per-thread microtile.
// Optional secondary output C2 gets columns >= c2_col0 (kv_cache slice).
// ============================================================================
#define BM 128
#define BN 128
#define BK 16
#define TM 8
#define TN 8
#define SPAD 4   // pad smem row stride to 132 floats (16B aligned, fewer conflicts)

__global__ void __launch_bounds__(256) gemm_nt_kernel(
    const float* __restrict__ A,
    const float* __restrict__ B,
    float* __restrict__ C,
    float* __restrict__ C2,
    int M, int N, int K, int c2_col0, int c2_ld)
{
    __shared__ float As[BK][BM + SPAD];
    __shared__ float Bs[BK][BN + SPAD];

    const int bm = blockIdx.y * BM;
    const int bn = blockIdx.x * BN;
    const int tid = threadIdx.x;
    const int tx = tid & 15;
    const int ty = tid >> 4;
    const int tm = ty * TM;
    const int tn = tx * TN;

    float acc[TM][TN];
#pragma unroll
    for (int i = 0; i < TM; i++)
#pragma unroll
        for (int j = 0; j < TN; j++) acc[i][j] = 0.0f;

    const float4* A4 = reinterpret_cast<const float4*>(A);
    const float4* B4 = reinterpret_cast<const float4*>(B);
    const int K4 = K >> 2;

    for (int k0 = 0; k0 < K; k0 += BK) {
#pragma unroll
        for (int it = 0; it < 2; it++) {
            int f = tid + it * 256;          // 0..511
            int row = f >> 2;                // 0..127
            int kq = (f & 3) << 2;           // 0,4,8,12
            float4 va = A4[(size_t)(bm + row) * K4 + ((k0 + kq) >> 2)];
            As[kq + 0][row] = va.x;
            As[kq + 1][row] = va.y;
            As[kq + 2][row] = va.z;
            As[kq + 3][row] = va.w;
            float4 vb = B4[(size_t)(bn + row) * K4 + ((k0 + kq) >> 2)];
            Bs[kq + 0][row] = vb.x;
            Bs[kq + 1][row] = vb.y;
            Bs[kq + 2][row] = vb.z;
            Bs[kq + 3][row] = vb.w;
        }
        __syncthreads();

#pragma unroll
        for (int k = 0; k < BK; k++) {
            float4 a0 = *reinterpret_cast<const float4*>(&As[k][tm]);
            float4 a1 = *reinterpret_cast<const float4*>(&As[k][tm + 4]);
            float4 b0 = *reinterpret_cast<const float4*>(&Bs[k][tn]);
            float4 b1 = *reinterpret_cast<const float4*>(&Bs[k][tn + 4]);
            float ar[TM] = {a0.x, a0.y, a0.z, a0.w, a1.x, a1.y, a1.z, a1.w};
            float br[TN] = {b0.x, b0.y, b0.z, b0.w, b1.x, b1.y, b1.z, b1.w};
#pragma unroll
            for (int i = 0; i < TM; i++)
#pragma unroll
                for (int j = 0; j < TN; j++)
                    acc[i][j] = fmaf(ar[i], br[j], acc[i][j]);
        }
        __syncthreads();
    }

    const bool kv_tile = (C2 != nullptr) && (bn >= c2_col0);
#pragma unroll
    for (int i = 0; i < TM; i++) {
        int row = bm + tm + i;
        float* cp = C + (size_t)row * N + bn + tn;
#pragma unroll
        for (int j = 0; j < TN; j += 4) {
            float4 v = make_float4(acc[i][j], acc[i][j + 1], acc[i][j + 2], acc[i][j + 3]);
            *reinterpret_cast<float4*>(cp + j) = v;
            if (kv_tile) {
                float* c2p = C2 + (size_t)row * c2_ld + (bn + tn + j - c2_col0);
                *reinterpret_cast<float4*>(c2p) = v;
            }
        }
    }
}

// ============================================================================
// Sliding-window GQA attention with ALiBi.
// grid = (qtile 0..3, head 0..15, block 0..15); 128 threads, 1 thread = 1 query.
// K/V staged in smem in 64-key chunks; all threads read the same (u,d) ->
// pure broadcast LDS. Online softmax with rescale-on-new-max (rare branch).
// ============================================================================
__global__ void __launch_bounds__(128) attn_kernel(
    const float* __restrict__ qkv, float* __restrict__ att)
{
    const int qt = blockIdx.x;         // query tile (128 queries)
    const int h  = blockIdx.y;         // q head
    const int n  = blockIdx.z;         // sequence block
    const int hk = h >> 2;             // kv head (group size 4)
    const int tid = threadIdx.x;
    const int a = qt * 128 + tid;      // query index within block (0..511)
    const int s_q = n * WIN + a;       // global query row

    const float scale = 0.125f;        // 64^-0.5
    const float slope = exp2f(-0.5f * (float)(h + 1));

    // load q (pre-scaled)
    float q[HD];
    {
        const float* qp = qkv + (size_t)s_q * QKV_N + h * HD;
#pragma unroll
        for (int d = 0; d < HD; d += 4) {
            float4 v = *reinterpret_cast<const float4*>(qp + d);
            q[d + 0] = v.x * scale;
            q[d + 1] = v.y * scale;
            q[d + 2] = v.z * scale;
            q[d + 3] = v.w * scale;
        }
    }

    float m = -1e30f, l = 0.0f;
    float o[HD];
#pragma unroll
    for (int d = 0; d < HD; d++) o[d] = 0.0f;

    __shared__ float Ks[64][HD];
    __shared__ float Vs[64][HD];

    const int c0 = qt * 2;             // first 64-key chunk needed
    for (int c = c0; c < c0 + 10; c++) {
        const int u0 = c * 64;
        __syncthreads();
        // load 64 keys + 64 values: 64 rows x 64 cols each.
        // 1024 float4 per tensor; 128 threads x 8 float4.
#pragma unroll
        for (int it = 0; it < 8; it++) {
            int f = tid + it * 128;
            int r = f >> 4;
            int col = (f & 15) << 2;
            int gk = (n - 1) * WIN + u0 + r;   // global key row (may be <0 for block 0)
            float4 vk = make_float4(0.f, 0.f, 0.f, 0.f);
            float4 vv = vk;
            if (gk >= 0) {
                const float* base = qkv + (size_t)gk * QKV_N;
                vk = *reinterpret_cast<const float4*>(base + (HQ + hk) * HD + col);
                vv = *reinterpret_cast<const float4*>(base + (HQ + HK + hk) * HD + col);
            }
            *reinterpret_cast<float4*>(&Ks[r][col]) = vk;
            *reinterpret_cast<float4*>(&Vs[r][col]) = vv;
        }
        __syncthreads();

        for (int r = 0; r < 64; r++) {
            const int u = u0 + r;
            const int diff = a + WIN - u;
            const bool valid = (diff >= 0) && (diff <= WIN) && ((n > 0) | (u >= WIN));
            if (!valid) continue;

            float s0 = 0.f, s1 = 0.f, s2 = 0.f, s3 = 0.f;
#pragma unroll
            for (int d4 = 0; d4 < 16; d4++) {
                float4 kk = *reinterpret_cast<const float4*>(&Ks[r][d4 << 2]);
                s0 = fmaf(q[(d4 << 2) + 0], kk.x, s0);
                s1 = fmaf(q[(d4 << 2) + 1], kk.y, s1);
                s2 = fmaf(q[(d4 << 2) + 2], kk.z, s2);
                s3 = fmaf(q[(d4 << 2) + 3], kk.w, s3);
            }
            float s = (s0 + s1) + (s2 + s3) - slope * (float)diff;

            if (s > m) {
                float corr = __expf(m - s);   // 0 on first key (m=-1e30)
                l *= corr;
#pragma unroll
                for (int d = 0; d < HD; d++) o[d] *= corr;
                m = s;
            }
            float p = __expf(s - m);
            l += p;
#pragma unroll
            for (int d4 = 0; d4 < 16; d4++) {
                float4 vv = *reinterpret_cast<const float4*>(&Vs[r][d4 << 2]);
                o[(d4 << 2) + 0] = fmaf(p, vv.x, o[(d4 << 2) + 0]);
                o[(d4 << 2) + 1] = fmaf(p, vv.y, o[(d4 << 2) + 1]);
                o[(d4 << 2) + 2] = fmaf(p, vv.z, o[(d4 << 2) + 2]);
                o[(d4 << 2) + 3] = fmaf(p, vv.w, o[(d4 << 2) + 3]);
            }
        }
    }

    const float inv = 1.0f / l;
    float* op = att + (size_t)s_q * D_MODEL + h * HD;
#pragma unroll
    for (int d = 0; d < HD; d += 4) {
        float4 v = make_float4(o[d] * inv, o[d + 1] * inv, o[d + 2] * inv, o[d + 3] * inv);
        *reinterpret_cast<float4*>(op + d) = v;
    }
}

// ============================================================================
// Host launcher
// ============================================================================
extern "C" void kernel_launch(void* const* d_in, const int* in_sizes, int n_in,
                              void* d_out, int out_size)
{
    const float* x     = (const float*)d_in[0];   // [8192, 1024]
    const float* Wqkv  = (const float*)d_in[1];   // [1536, 1024]
    const float* Wproj = (const float*)d_in[2];   // [1024, 1024]

    float* out = (float*)d_out;                          // [8192, 1024]
    float* kv  = out + (size_t)S_LEN * D_MODEL;          // [8192, 8, 64]

    float* qkv = nullptr;
    float* att = nullptr;
    cudaGetSymbolAddress((void**)&qkv, g_qkv);
    cudaGetSymbolAddress((void**)&att, g_att);

    // 1) QKV GEMM: [8192,1536] = x @ Wqkv^T ; kv_cache slice written on the fly
    gemm_nt_kernel<<<dim3(QKV_N / BN, S_LEN / BM), 256>>>(
        x, Wqkv, qkv, kv, S_LEN, QKV_N, D_MODEL, KV_COL0, KV_LD);

    // 2) sliding-window attention -> att [8192, 1024]
    attn_kernel<<<dim3(4, HQ, NB), 128>>>(qkv, att);

    // 3) projection: out = att @ Wproj^T
    gemm_nt_kernel<<<dim3(D_MODEL / BN, S_LEN / BM), 256>>>(
        att, Wproj, out, nullptr, S_LEN, D_MODEL, D_MODEL, 0, 0);
}

// round 3
// speedup vs baseline: 1.5162x; 1.5162x over previous
#include <cuda_runtime.h>
#include <cuda_bf16.h>
#include <cstdint>

// Problem constants (B=1, S=8192, D=1024, Hq=16, Hk=4, hd=64, W=512)
#define S_LEN   8192
#define D_MODEL 1024
#define QKV_N   1536
#define HQ      16
#define HK      4
#define HD      64
#define WIN     512
#define NB      16
#define KV_COL0 1024
#define KV_LD   512
#define GK      1024          // K dim for both GEMMs
#define STRD    20            // smem row stride (floats): conflict-free frag gather

// -------- scratch (device globals: allocation-guard-safe) --------
__device__ float g_qkv[(size_t)S_LEN * QKV_N];
__device__ float g_att[(size_t)S_LEN * D_MODEL];

__device__ __forceinline__ uint32_t smem_u32(const void* p) {
    uint32_t a;
    asm("{ .reg .u64 t; cvta.to.shared.u64 t, %1; cvt.u32.u64 %0, t; }" : "=r"(a) : "l"(p));
    return a;
}
__device__ __forceinline__ uint32_t f2tf32(float x) {
    uint32_t u;
    asm("cvt.rna.tf32.f32 %0, %1;" : "=r"(u) : "f"(x));
    return u;
}
__device__ __forceinline__ void mma_tf32(float c[4], const uint32_t a[4], const uint32_t b[2]) {
    asm volatile(
        "mma.sync.aligned.m16n8k8.row.col.f32.tf32.tf32.f32 "
        "{%0,%1,%2,%3}, {%4,%5,%6,%7}, {%8,%9}, {%0,%1,%2,%3};"
        : "+f"(c[0]), "+f"(c[1]), "+f"(c[2]), "+f"(c[3])
        : "r"(a[0]), "r"(a[1]), "r"(a[2]), "r"(a[3]), "r"(b[0]), "r"(b[1]));
}

// ============================================================================
// tf32 mma.sync GEMM: C[M,N] = A[M,1024] * B[N,1024]^T.
// CTA 128x128, 8 warps (2M x 4N), warp tile 64x32, BK=16, cp.async 2-stage.
// Optional C2 gets columns >= c2_col0 (kv_cache slice).
// ============================================================================
__global__ void __launch_bounds__(256) gemm_mma_kernel(
    const float* __restrict__ A, const float* __restrict__ B,
    float* __restrict__ C, float* __restrict__ C2,
    int N, int c2_col0, int c2_ld)
{
    __shared__ float As[2][128 * STRD];
    __shared__ float Bs[2][128 * STRD];

    const int tid = threadIdx.x;
    const int wid = tid >> 5, lane = tid & 31;
    const int g = lane >> 2, tg = lane & 3;
    const int wm = (wid & 1) * 64;        // warp M offset in tile
    const int wn = (wid >> 1) * 32;       // warp N offset in tile
    const int bm = blockIdx.y * 128, bn = blockIdx.x * 128;

    const uint32_t sA = smem_u32(&As[0][0]);
    const uint32_t sB = smem_u32(&Bs[0][0]);

    float acc[4][4][4];
#pragma unroll
    for (int i = 0; i < 4; i++)
#pragma unroll
        for (int j = 0; j < 4; j++)
#pragma unroll
            for (int r = 0; r < 4; r++) acc[i][j][r] = 0.0f;

    // ---- cp.async stage fill: A/B tiles are 128 rows x 16 floats (4 float4/row)
    auto issue = [&](int kc) {
        const int st = kc & 1;
        const uint32_t soff = (uint32_t)st * (128 * STRD * 4);
#pragma unroll
        for (int i = 0; i < 2; i++) {
            const int idx = tid + i * 256;        // 0..511
            const int row = idx >> 2, q = idx & 3;
            const uint32_t sm = (uint32_t)(row * STRD + q * 4) * 4 + soff;
            const float* ga = A + (size_t)(bm + row) * GK + kc * 16 + q * 4;
            asm volatile("cp.async.cg.shared.global [%0], [%1], 16;" :: "r"(sA + sm), "l"(ga));
            const float* gb = B + (size_t)(bn + row) * GK + kc * 16 + q * 4;
            asm volatile("cp.async.cg.shared.global [%0], [%1], 16;" :: "r"(sB + sm), "l"(gb));
        }
        asm volatile("cp.async.commit_group;" ::: "memory");
    };

    issue(0);
    issue(1);

    const int NKC = GK / 16;   // 64
    for (int kc = 0; kc < NKC; kc++) {
        const int st = kc & 1;
        if (kc == NKC - 1) asm volatile("cp.async.wait_group 0;" ::: "memory");
        else               asm volatile("cp.async.wait_group 1;" ::: "memory");
        __syncthreads();

        const float* Ab = &As[st][0];
        const float* Bb = &Bs[st][0];
#pragma unroll
        for (int ks = 0; ks < 2; ks++) {
            const int k0 = ks * 8;
            uint32_t af[4][4], bf[4][2];
#pragma unroll
            for (int im = 0; im < 4; im++) {
                const int m = wm + im * 16 + g;
                af[im][0] = f2tf32(Ab[m * STRD + k0 + tg]);
                af[im][1] = f2tf32(Ab[(m + 8) * STRD + k0 + tg]);
                af[im][2] = f2tf32(Ab[m * STRD + k0 + tg + 4]);
                af[im][3] = f2tf32(Ab[(m + 8) * STRD + k0 + tg + 4]);
            }
#pragma unroll
            for (int in_ = 0; in_ < 4; in_++) {
                const int n = wn + in_ * 8 + g;
                bf[in_][0] = f2tf32(Bb[n * STRD + k0 + tg]);
                bf[in_][1] = f2tf32(Bb[n * STRD + k0 + tg + 4]);
            }
#pragma unroll
            for (int im = 0; im < 4; im++)
#pragma unroll
                for (int in_ = 0; in_ < 4; in_++)
                    mma_tf32(acc[im][in_], af[im], bf[in_]);
        }
        __syncthreads();
        if (kc + 2 < NKC) issue(kc + 2);
    }

    // ---- epilogue: c0/c1 at (row, 2tg), c2/c3 at (row+8, 2tg)
    const bool kvt = (C2 != nullptr) && (bn >= c2_col0);
#pragma unroll
    for (int im = 0; im < 4; im++) {
        const int row0 = bm + wm + im * 16 + g;
#pragma unroll
        for (int in_ = 0; in_ < 4; in_++) {
            const int col = bn + wn + in_ * 8 + 2 * tg;
            float2 v0 = make_float2(acc[im][in_][0], acc[im][in_][1]);
            float2 v1 = make_float2(acc[im][in_][2], acc[im][in_][3]);
            *reinterpret_cast<float2*>(C + (size_t)row0 * N + col) = v0;
            *reinterpret_cast<float2*>(C + (size_t)(row0 + 8) * N + col) = v1;
            if (kvt) {
                const int c2c = col - c2_col0;
                *reinterpret_cast<float2*>(C2 + (size_t)row0 * c2_ld + c2c) = v0;
                *reinterpret_cast<float2*>(C2 + (size_t)(row0 + 8) * c2_ld + c2c) = v1;
            }
        }
    }
}

// ============================================================================
// Sliding-window GQA attention with ALiBi (SIMT fp32, unchanged).
// ============================================================================
__global__ void __launch_bounds__(128) attn_kernel(
    const float* __restrict__ qkv, float* __restrict__ att)
{
    const int qt = blockIdx.x;
    const int h  = blockIdx.y;
    const int n  = blockIdx.z;
    const int hk = h >> 2;
    const int tid = threadIdx.x;
    const int a = qt * 128 + tid;
    const int s_q = n * WIN + a;

    const float scale = 0.125f;
    const float slope = exp2f(-0.5f * (float)(h + 1));

    float q[HD];
    {
        const float* qp = qkv + (size_t)s_q * QKV_N + h * HD;
#pragma unroll
        for (int d = 0; d < HD; d += 4) {
            float4 v = *reinterpret_cast<const float4*>(qp + d);
            q[d + 0] = v.x * scale; q[d + 1] = v.y * scale;
            q[d + 2] = v.z * scale; q[d + 3] = v.w * scale;
        }
    }

    float m = -1e30f, l = 0.0f;
    float o[HD];
#pragma unroll
    for (int d = 0; d < HD; d++) o[d] = 0.0f;

    __shared__ float Ks[64][HD];
    __shared__ float Vs[64][HD];

    const int c0 = qt * 2;
    for (int c = c0; c < c0 + 10; c++) {
        const int u0 = c * 64;
        __syncthreads();
#pragma unroll
        for (int it = 0; it < 8; it++) {
            int f = tid + it * 128;
            int r = f >> 4;
            int col = (f & 15) << 2;
            int gk = (n - 1) * WIN + u0 + r;
            float4 vk = make_float4(0.f, 0.f, 0.f, 0.f);
            float4 vv = vk;
            if (gk >= 0) {
                const float* base = qkv + (size_t)gk * QKV_N;
                vk = *reinterpret_cast<const float4*>(base + (HQ + hk) * HD + col);
                vv = *reinterpret_cast<const float4*>(base + (HQ + HK + hk) * HD + col);
            }
            *reinterpret_cast<float4*>(&Ks[r][col]) = vk;
            *reinterpret_cast<float4*>(&Vs[r][col]) = vv;
        }
        __syncthreads();

        for (int r = 0; r < 64; r++) {
            const int u = u0 + r;
            const int diff = a + WIN - u;
            const bool valid = (diff >= 0) && (diff <= WIN) && ((n > 0) | (u >= WIN));
            if (!valid) continue;

            float s0 = 0.f, s1 = 0.f, s2 = 0.f, s3 = 0.f;
#pragma unroll
            for (int d4 = 0; d4 < 16; d4++) {
                float4 kk = *reinterpret_cast<const float4*>(&Ks[r][d4 << 2]);
                s0 = fmaf(q[(d4 << 2) + 0], kk.x, s0);
                s1 = fmaf(q[(d4 << 2) + 1], kk.y, s1);
                s2 = fmaf(q[(d4 << 2) + 2], kk.z, s2);
                s3 = fmaf(q[(d4 << 2) + 3], kk.w, s3);
            }
            float s = (s0 + s1) + (s2 + s3) - slope * (float)diff;

            if (s > m) {
                float corr = __expf(m - s);
                l *= corr;
#pragma unroll
                for (int d = 0; d < HD; d++) o[d] *= corr;
                m = s;
            }
            float p = __expf(s - m);
            l += p;
#pragma unroll
            for (int d4 = 0; d4 < 16; d4++) {
                float4 vv = *reinterpret_cast<const float4*>(&Vs[r][d4 << 2]);
                o[(d4 << 2) + 0] = fmaf(p, vv.x, o[(d4 << 2) + 0]);
                o[(d4 << 2) + 1] = fmaf(p, vv.y, o[(d4 << 2) + 1]);
                o[(d4 << 2) + 2] = fmaf(p, vv.z, o[(d4 << 2) + 2]);
                o[(d4 << 2) + 3] = fmaf(p, vv.w, o[(d4 << 2) + 3]);
            }
        }
    }

    const float inv = 1.0f / l;
    float* op = att + (size_t)s_q * D_MODEL + h * HD;
#pragma unroll
    for (int d = 0; d < HD; d += 4) {
        float4 v = make_float4(o[d] * inv, o[d + 1] * inv, o[d + 2] * inv, o[d + 3] * inv);
        *reinterpret_cast<float4*>(op + d) = v;
    }
}

// ============================================================================
// Host launcher
// ============================================================================
extern "C" void kernel_launch(void* const* d_in, const int* in_sizes, int n_in,
                              void* d_out, int out_size)
{
    const float* x     = (const float*)d_in[0];
    const float* Wqkv  = (const float*)d_in[1];
    const float* Wproj = (const float*)d_in[2];

    float* out = (float*)d_out;
    float* kv  = out + (size_t)S_LEN * D_MODEL;

    float* qkv = nullptr;
    float* att = nullptr;
    cudaGetSymbolAddress((void**)&qkv, g_qkv);
    cudaGetSymbolAddress((void**)&att, g_att);

    // 1) QKV GEMM (tf32 mma.sync): [8192,1536]; kv_cache slice fused
    gemm_mma_kernel<<<dim3(QKV_N / 128, S_LEN / 128), 256>>>(
        x, Wqkv, qkv, kv, QKV_N, KV_COL0, KV_LD);

    // 2) sliding-window attention -> att [8192, 1024]
    attn_kernel<<<dim3(4, HQ, NB), 128>>>(qkv, att);

    // 3) projection GEMM (tf32 mma.sync): out = att @ Wproj^T
    gemm_mma_kernel<<<dim3(D_MODEL / 128, S_LEN / 128), 256>>>(
        att, Wproj, out, nullptr, D_MODEL, 0, 0);
}

// round 4
// speedup vs baseline: 2.4720x; 1.6303x over previous
#include <cuda_runtime.h>
#include <cuda_bf16.h>
#include <cstdint>

// Problem constants (B=1, S=8192, D=1024, Hq=16, Hk=4, hd=64, W=512)
#define S_LEN   8192
#define D_MODEL 1024
#define QKV_N   1536
#define HQ      16
#define HK      4
#define HD      64
#define WIN     512
#define NB      16
#define KV_COL0 1024
#define KV_LD   512
#define GK      1024
#define STRD    20
#define FULLM   0xffffffffu

__device__ float g_qkv[(size_t)S_LEN * QKV_N];
__device__ float g_att[(size_t)S_LEN * D_MODEL];

__device__ __forceinline__ uint32_t smem_u32(const void* p) {
    uint32_t a;
    asm("{ .reg .u64 t; cvta.to.shared.u64 t, %1; cvt.u32.u64 %0, t; }" : "=r"(a) : "l"(p));
    return a;
}
__device__ __forceinline__ uint32_t f2tf32(float x) {
    uint32_t u;
    asm("cvt.rna.tf32.f32 %0, %1;" : "=r"(u) : "f"(x));
    return u;
}
__device__ __forceinline__ float ex2f(float x) {
    float y;
    asm("ex2.approx.f32 %0, %1;" : "=f"(y) : "f"(x));
    return y;
}
__device__ __forceinline__ void mma_tf32(float c[4], const uint32_t a[4], uint32_t b0, uint32_t b1) {
    asm volatile(
        "mma.sync.aligned.m16n8k8.row.col.f32.tf32.tf32.f32 "
        "{%0,%1,%2,%3}, {%4,%5,%6,%7}, {%8,%9}, {%0,%1,%2,%3};"
        : "+f"(c[0]), "+f"(c[1]), "+f"(c[2]), "+f"(c[3])
        : "r"(a[0]), "r"(a[1]), "r"(a[2]), "r"(a[3]), "r"(b0), "r"(b1));
}

// ============================================================================
// tf32 mma.sync GEMM (unchanged from R3): C[M,N] = A[M,1024]*B[N,1024]^T
// ============================================================================
__global__ void __launch_bounds__(256) gemm_mma_kernel(
    const float* __restrict__ A, const float* __restrict__ B,
    float* __restrict__ C, float* __restrict__ C2,
    int N, int c2_col0, int c2_ld)
{
    __shared__ float As[2][128 * STRD];
    __shared__ float Bs[2][128 * STRD];

    const int tid = threadIdx.x;
    const int wid = tid >> 5, lane = tid & 31;
    const int g = lane >> 2, tg = lane & 3;
    const int wm = (wid & 1) * 64;
    const int wn = (wid >> 1) * 32;
    const int bm = blockIdx.y * 128, bn = blockIdx.x * 128;

    const uint32_t sA = smem_u32(&As[0][0]);
    const uint32_t sB = smem_u32(&Bs[0][0]);

    float acc[4][4][4];
#pragma unroll
    for (int i = 0; i < 4; i++)
#pragma unroll
        for (int j = 0; j < 4; j++)
#pragma unroll
            for (int r = 0; r < 4; r++) acc[i][j][r] = 0.0f;

    auto issue = [&](int kc) {
        const int st = kc & 1;
        const uint32_t soff = (uint32_t)st * (128 * STRD * 4);
#pragma unroll
        for (int i = 0; i < 2; i++) {
            const int idx = tid + i * 256;
            const int row = idx >> 2, q = idx & 3;
            const uint32_t sm = (uint32_t)(row * STRD + q * 4) * 4 + soff;
            const float* ga = A + (size_t)(bm + row) * GK + kc * 16 + q * 4;
            asm volatile("cp.async.cg.shared.global [%0], [%1], 16;" :: "r"(sA + sm), "l"(ga));
            const float* gb = B + (size_t)(bn + row) * GK + kc * 16 + q * 4;
            asm volatile("cp.async.cg.shared.global [%0], [%1], 16;" :: "r"(sB + sm), "l"(gb));
        }
        asm volatile("cp.async.commit_group;" ::: "memory");
    };

    issue(0);
    issue(1);

    const int NKC = GK / 16;
    for (int kc = 0; kc < NKC; kc++) {
        const int st = kc & 1;
        if (kc == NKC - 1) asm volatile("cp.async.wait_group 0;" ::: "memory");
        else               asm volatile("cp.async.wait_group 1;" ::: "memory");
        __syncthreads();

        const float* Ab = &As[st][0];
        const float* Bb = &Bs[st][0];
#pragma unroll
        for (int ks = 0; ks < 2; ks++) {
            const int k0 = ks * 8;
            uint32_t af[4][4], bf[4][2];
#pragma unroll
            for (int im = 0; im < 4; im++) {
                const int m = wm + im * 16 + g;
                af[im][0] = f2tf32(Ab[m * STRD + k0 + tg]);
                af[im][1] = f2tf32(Ab[(m + 8) * STRD + k0 + tg]);
                af[im][2] = f2tf32(Ab[m * STRD + k0 + tg + 4]);
                af[im][3] = f2tf32(Ab[(m + 8) * STRD + k0 + tg + 4]);
            }
#pragma unroll
            for (int in_ = 0; in_ < 4; in_++) {
                const int n = wn + in_ * 8 + g;
                bf[in_][0] = f2tf32(Bb[n * STRD + k0 + tg]);
                bf[in_][1] = f2tf32(Bb[n * STRD + k0 + tg + 4]);
            }
#pragma unroll
            for (int im = 0; im < 4; im++)
#pragma unroll
                for (int in_ = 0; in_ < 4; in_++)
                    mma_tf32(acc[im][in_], af[im], bf[in_][0], bf[in_][1]);
        }
        __syncthreads();
        if (kc + 2 < NKC) issue(kc + 2);
    }

    const bool kvt = (C2 != nullptr) && (bn >= c2_col0);
#pragma unroll
    for (int im = 0; im < 4; im++) {
        const int row0 = bm + wm + im * 16 + g;
#pragma unroll
        for (int in_ = 0; in_ < 4; in_++) {
            const int col = bn + wn + in_ * 8 + 2 * tg;
            float2 v0 = make_float2(acc[im][in_][0], acc[im][in_][1]);
            float2 v1 = make_float2(acc[im][in_][2], acc[im][in_][3]);
            *reinterpret_cast<float2*>(C + (size_t)row0 * N + col) = v0;
            *reinterpret_cast<float2*>(C + (size_t)(row0 + 8) * N + col) = v1;
            if (kvt) {
                const int c2c = col - c2_col0;
                *reinterpret_cast<float2*>(C2 + (size_t)row0 * c2_ld + c2c) = v0;
                *reinterpret_cast<float2*>(C2 + (size_t)(row0 + 8) * c2_ld + c2c) = v1;
            }
        }
    }
}

// ============================================================================
// Flash attention with mma.sync tf32.
// CTA = 128 queries x 1 head; 8 warps x 16 rows. 64-key chunks, 10 chunks.
// K smem stride 68 floats, V stride 72 (both conflict-free for B-frag gather).
// Base-2 softmax; per-row ALiBi constant dropped (softmax shift invariance).
// ============================================================================
#define KS_ST 68
#define VS_ST 72
#define KS_FL (64 * KS_ST)          // 4352 floats per stage
#define VS_FL (64 * VS_ST)          // 4608 floats per stage
#define ATT_SMEM ((2 * KS_FL + 2 * VS_FL) * 4)   // 71680 bytes

__global__ void __launch_bounds__(256, 2) attn_mma_kernel(
    const float* __restrict__ qkv, float* __restrict__ att)
{
    extern __shared__ float sm[];
    const int qt = blockIdx.x, h = blockIdx.y, n = blockIdx.z, hk = h >> 2;
    const int tid = threadIdx.x, wid = tid >> 5, lane = tid & 31;
    const int g = lane >> 2, tg = lane & 3;
    const int abase = qt * 128 + wid * 16;
    const int a0 = abase + g, a1 = a0 + 8;
    const float qscale = 0.125f * 1.44269504f;
    const float slope2 = exp2f(-0.5f * (float)(h + 1)) * 1.44269504f;
    const uint32_t smb = smem_u32(sm);
    const bool nz = (n > 0);

    // Q fragments (scale folded), persistent
    uint32_t qf[8][4];
    {
        const float* q0 = qkv + (size_t)(n * WIN + a0) * QKV_N + h * HD;
        const float* q1 = qkv + (size_t)(n * WIN + a1) * QKV_N + h * HD;
#pragma unroll
        for (int kc = 0; kc < 8; kc++) {
            qf[kc][0] = f2tf32(q0[kc * 8 + tg] * qscale);
            qf[kc][1] = f2tf32(q1[kc * 8 + tg] * qscale);
            qf[kc][2] = f2tf32(q0[kc * 8 + tg + 4] * qscale);
            qf[kc][3] = f2tf32(q1[kc * 8 + tg + 4] * qscale);
        }
    }

    float o[8][4];
#pragma unroll
    for (int i = 0; i < 8; i++)
#pragma unroll
        for (int j = 0; j < 4; j++) o[i][j] = 0.0f;
    float m0 = -1e30f, m1 = -1e30f, l0 = 0.0f, l1 = 0.0f;

    auto issue = [&](int ci) {
        const int st = ci & 1;
        const uint32_t kbase = smb + (uint32_t)st * KS_FL * 4;
        const uint32_t vbase = smb + (uint32_t)(2 * KS_FL + st * VS_FL) * 4;
        const int u0 = ci * 64;
#pragma unroll
        for (int i = 0; i < 4; i++) {
            const int idx = tid + i * 256;
            const int r = idx >> 4, c4 = idx & 15;
            const int gk = (n - 1) * WIN + u0 + r;
            const int pr = (gk >= 0) ? 16 : 0;
            const size_t base = (size_t)(gk >= 0 ? gk : 0) * QKV_N;
            const float* ks = qkv + base + (HQ + hk) * HD + c4 * 4;
            const float* vs = qkv + base + (HQ + HK + hk) * HD + c4 * 4;
            const uint32_t kd = kbase + (uint32_t)(r * KS_ST + c4 * 4) * 4;
            const uint32_t vd = vbase + (uint32_t)(r * VS_ST + c4 * 4) * 4;
            asm volatile("cp.async.cg.shared.global [%0], [%1], 16, %2;" :: "r"(kd), "l"(ks), "r"(pr));
            asm volatile("cp.async.cg.shared.global [%0], [%1], 16, %2;" :: "r"(vd), "l"(vs), "r"(pr));
        }
        asm volatile("cp.async.commit_group;" ::: "memory");
    };

    const int c0 = qt * 2;
    issue(c0);
    issue(c0 + 1);

    for (int ci = c0; ci < c0 + 10; ci++) {
        const int st = ci & 1;
        if (ci == c0 + 9) asm volatile("cp.async.wait_group 0;" ::: "memory");
        else              asm volatile("cp.async.wait_group 1;" ::: "memory");
        __syncthreads();

        const float* Kst = sm + st * KS_FL;
        const float* Vst = sm + 2 * KS_FL + st * VS_FL;
        const int u0 = ci * 64;

        // ---- S = Q K^T (per warp: 16 rows x 64 keys)
        float sacc[8][4];
#pragma unroll
        for (int nt = 0; nt < 8; nt++)
#pragma unroll
            for (int j = 0; j < 4; j++) sacc[nt][j] = 0.0f;

#pragma unroll
        for (int nt = 0; nt < 8; nt++) {
            const float* kr = Kst + (nt * 8 + g) * KS_ST;
#pragma unroll
            for (int kc = 0; kc < 8; kc++) {
                uint32_t b0 = __float_as_uint(kr[kc * 8 + tg]);      // raw bits as tf32
                uint32_t b1 = __float_as_uint(kr[kc * 8 + tg + 4]);
                mma_tf32(sacc[nt], qf[kc], b0, b1);
            }
        }

        // ---- mask + column ALiBi bias + row max
        float mx0 = -1e30f, mx1 = -1e30f;
#pragma unroll
        for (int nt = 0; nt < 8; nt++) {
            const int ub = u0 + nt * 8 + 2 * tg;
#pragma unroll
            for (int j = 0; j < 4; j++) {
                const int u = ub + (j & 1);
                const int a = (j < 2) ? a0 : a1;
                const int diff = a + WIN - u;
                const bool ok = ((unsigned)diff <= (unsigned)WIN) && (nz || (u >= WIN));
                float s = ok ? (sacc[nt][j] + slope2 * (float)u) : -1e30f;
                sacc[nt][j] = s;
                if (j < 2) mx0 = fmaxf(mx0, s);
                else       mx1 = fmaxf(mx1, s);
            }
        }
        mx0 = fmaxf(mx0, __shfl_xor_sync(FULLM, mx0, 1));
        mx0 = fmaxf(mx0, __shfl_xor_sync(FULLM, mx0, 2));
        mx1 = fmaxf(mx1, __shfl_xor_sync(FULLM, mx1, 1));
        mx1 = fmaxf(mx1, __shfl_xor_sync(FULLM, mx1, 2));

        const float nm0 = fmaxf(m0, mx0), nm1 = fmaxf(m1, mx1);
        const float cr0 = ex2f(m0 - nm0), cr1 = ex2f(m1 - nm1);
        l0 *= cr0; l1 *= cr1; m0 = nm0; m1 = nm1;
#pragma unroll
        for (int nt = 0; nt < 8; nt++) {
            o[nt][0] *= cr0; o[nt][1] *= cr0;
            o[nt][2] *= cr1; o[nt][3] *= cr1;
        }

        // ---- p = exp2(s - m), zero masked, accumulate l
#pragma unroll
        for (int nt = 0; nt < 8; nt++) {
#pragma unroll
            for (int j = 0; j < 4; j++) {
                const float s = sacc[nt][j];
                float p = ex2f(s - ((j < 2) ? nm0 : nm1));
                p = (s < -5e29f) ? 0.0f : p;
                sacc[nt][j] = p;
                if (j < 2) l0 += p; else l1 += p;
            }
        }

        // ---- O += P V  (P relayout via shuffles per 8-key chunk)
        const int s1 = g * 4 + (tg >> 1), s2 = s1 + 2;
        const bool odd = tg & 1;
#pragma unroll
        for (int kc = 0; kc < 8; kc++) {
            const float w00 = __shfl_sync(FULLM, sacc[kc][0], s1);
            const float w01 = __shfl_sync(FULLM, sacc[kc][1], s1);
            const float w02 = __shfl_sync(FULLM, sacc[kc][2], s1);
            const float w03 = __shfl_sync(FULLM, sacc[kc][3], s1);
            const float w10 = __shfl_sync(FULLM, sacc[kc][0], s2);
            const float w11 = __shfl_sync(FULLM, sacc[kc][1], s2);
            const float w12 = __shfl_sync(FULLM, sacc[kc][2], s2);
            const float w13 = __shfl_sync(FULLM, sacc[kc][3], s2);
            uint32_t pa[4];
            pa[0] = f2tf32(odd ? w01 : w00);   // P[a0][kc*8+tg]
            pa[1] = f2tf32(odd ? w03 : w02);   // P[a1][kc*8+tg]
            pa[2] = f2tf32(odd ? w11 : w10);   // P[a0][kc*8+tg+4]
            pa[3] = f2tf32(odd ? w13 : w12);   // P[a1][kc*8+tg+4]

            const float* vr0 = Vst + (kc * 8 + tg) * VS_ST;
            const float* vr1 = Vst + (kc * 8 + tg + 4) * VS_ST;
#pragma unroll
            for (int ntd = 0; ntd < 8; ntd++) {
                uint32_t b0 = __float_as_uint(vr0[ntd * 8 + g]);
                uint32_t b1 = __float_as_uint(vr1[ntd * 8 + g]);
                mma_tf32(o[ntd], pa, b0, b1);
            }
        }

        __syncthreads();
        if (ci + 2 < c0 + 10) issue(ci + 2);
    }

    // ---- finalize: row sums, normalize, store
    l0 += __shfl_xor_sync(FULLM, l0, 1);
    l0 += __shfl_xor_sync(FULLM, l0, 2);
    l1 += __shfl_xor_sync(FULLM, l1, 1);
    l1 += __shfl_xor_sync(FULLM, l1, 2);
    const float i0 = 1.0f / l0, i1 = 1.0f / l1;

    float* o0 = att + (size_t)(n * WIN + a0) * D_MODEL + h * HD;
    float* o1 = att + (size_t)(n * WIN + a1) * D_MODEL + h * HD;
#pragma unroll
    for (int ntd = 0; ntd < 8; ntd++) {
        const int d = ntd * 8 + 2 * tg;
        *reinterpret_cast<float2*>(o0 + d) = make_float2(o[ntd][0] * i0, o[ntd][1] * i0);
        *reinterpret_cast<float2*>(o1 + d) = make_float2(o[ntd][2] * i1, o[ntd][3] * i1);
    }
}

// ============================================================================
// Host launcher
// ============================================================================
extern "C" void kernel_launch(void* const* d_in, const int* in_sizes, int n_in,
                              void* d_out, int out_size)
{
    const float* x     = (const float*)d_in[0];
    const float* Wqkv  = (const float*)d_in[1];
    const float* Wproj = (const float*)d_in[2];

    float* out = (float*)d_out;
    float* kv  = out + (size_t)S_LEN * D_MODEL;

    float* qkv = nullptr;
    float* att = nullptr;
    cudaGetSymbolAddress((void**)&qkv, g_qkv);
    cudaGetSymbolAddress((void**)&att, g_att);

    cudaFuncSetAttribute(attn_mma_kernel,
                         cudaFuncAttributeMaxDynamicSharedMemorySize, ATT_SMEM);

    gemm_mma_kernel<<<dim3(QKV_N / 128, S_LEN / 128), 256>>>(
        x, Wqkv, qkv, kv, QKV_N, KV_COL0, KV_LD);

    attn_mma_kernel<<<dim3(4, HQ, NB), 256, ATT_SMEM>>>(qkv, att);

    gemm_mma_kernel<<<dim3(D_MODEL / 128, S_LEN / 128), 256>>>(
        att, Wproj, out, nullptr, D_MODEL, 0, 0);
}

// round 6
// speedup vs baseline: 4.1200x; 1.6667x over previous
#include <cuda_runtime.h>
#include <cuda_bf16.h>
#include <cstdint>

// Problem constants (B=1, S=8192, D=1024, Hq=16, Hk=4, hd=64, W=512)
#define S_LEN   8192
#define D_MODEL 1024
#define QKV_N   1536
#define HQ      16
#define HK      4
#define HD      64
#define WIN     512
#define NB      16
#define KV_COL0 1024
#define KV_LD   512
#define GK      1024
#define FULLM   0xffffffffu

__device__ float g_qkv[(size_t)S_LEN * QKV_N];
__device__ float g_att[(size_t)S_LEN * D_MODEL];
__device__ float g_xr[(size_t)S_LEN * D_MODEL];
__device__ float g_wqkvr[(size_t)QKV_N * D_MODEL];
__device__ float g_wprojr[(size_t)D_MODEL * D_MODEL];

__device__ __forceinline__ uint32_t smem_u32(const void* p) {
    uint32_t a;
    asm("{ .reg .u64 t; cvta.to.shared.u64 t, %1; cvt.u32.u64 %0, t; }" : "=r"(a) : "l"(p));
    return a;
}
__device__ __forceinline__ uint32_t f2tf32(float x) {
    uint32_t u;
    asm("cvt.rna.tf32.f32 %0, %1;" : "=r"(u) : "f"(x));
    return u;
}
__device__ __forceinline__ float ex2f(float x) {
    float y;
    asm("ex2.approx.f32 %0, %1;" : "=f"(y) : "f"(x));
    return y;
}
__device__ __forceinline__ void mma_tf32(float c[4], const uint32_t a[4], uint32_t b0, uint32_t b1) {
    asm volatile(
        "mma.sync.aligned.m16n8k8.row.col.f32.tf32.tf32.f32 "
        "{%0,%1,%2,%3}, {%4,%5,%6,%7}, {%8,%9}, {%0,%1,%2,%3};"
        : "+f"(c[0]), "+f"(c[1]), "+f"(c[2]), "+f"(c[3])
        : "r"(a[0]), "r"(a[1]), "r"(a[2]), "r"(a[3]), "r"(b0), "r"(b1));
}
__device__ __forceinline__ void ldsm4(uint32_t& r0, uint32_t& r1, uint32_t& r2, uint32_t& r3, uint32_t a) {
    asm volatile("ldmatrix.sync.aligned.m8n8.x4.shared.b16 {%0,%1,%2,%3}, [%4];"
        : "=r"(r0), "=r"(r1), "=r"(r2), "=r"(r3) : "r"(a));
}

// ============================================================================
// Pre-round to tf32 (rna), elementwise, float4 granularity.
// ============================================================================
__global__ void __launch_bounds__(256) round_kernel(
    const float* __restrict__ src, float* __restrict__ dst, int n4)
{
    int i = blockIdx.x * blockDim.x + threadIdx.x;
    int stride = gridDim.x * blockDim.x;
    for (; i < n4; i += stride) {
        float4 v = reinterpret_cast<const float4*>(src)[i];
        v.x = __uint_as_float(f2tf32(v.x));
        v.y = __uint_as_float(f2tf32(v.y));
        v.z = __uint_as_float(f2tf32(v.z));
        v.w = __uint_as_float(f2tf32(v.w));
        reinterpret_cast<float4*>(dst)[i] = v;
    }
}

// ============================================================================
// tf32 mma.sync GEMM with ldmatrix fragments + 4-stage cp.async pipeline.
// C[M,N] = A[M,1024]*B[N,1024]^T, CTA 128x128, 8 warps (2M x 4N).
// Inputs must be pre-rounded to tf32. Optional C2 gets cols >= c2_col0.
// ============================================================================
#define GST 20                      // smem row stride (floats) — LDSM conflict-free
#define STG_FL (128 * GST)          // 2560 floats per tensor per stage
#define STAGE_FL (2 * STG_FL)       // 5120
#define GEMM_SMEM (4 * STAGE_FL * 4)  // 81920 bytes

__global__ void __launch_bounds__(256) gemm_mma_kernel(
    const float* __restrict__ A, const float* __restrict__ B,
    float* __restrict__ C, float* __restrict__ C2,
    int N, int c2_col0, int c2_ld)
{
    extern __shared__ float gsm[];
    const uint32_t smb = smem_u32(gsm);

    const int tid = threadIdx.x;
    const int wid = tid >> 5, lane = tid & 31;
    const int g = lane >> 2, tg = lane & 3;
    const int lr = lane & 7, lm = lane >> 3;
    const int wm = (wid & 1) * 64;
    const int wn = (wid >> 1) * 32;
    const int bm = blockIdx.y * 128, bn = blockIdx.x * 128;

    // ldsm per-thread base byte offsets (within stage tensor)
    const uint32_t aB0 = (uint32_t)(((wm + (lm & 1) * 8 + lr) * GST + (lm >> 1) * 4) * 4);
    const uint32_t bB0 = (uint32_t)(((wn + (lm >> 1) * 8 + lr) * GST + (lm & 1) * 4) * 4);

    float acc[4][4][4];
#pragma unroll
    for (int i = 0; i < 4; i++)
#pragma unroll
        for (int j = 0; j < 4; j++)
#pragma unroll
            for (int r = 0; r < 4; r++) acc[i][j][r] = 0.0f;

    auto issue = [&](int kc) {
        const int st = kc & 3;
        const uint32_t sa = smb + (uint32_t)st * STAGE_FL * 4;
        const uint32_t sb = sa + STG_FL * 4;
#pragma unroll
        for (int i = 0; i < 2; i++) {
            const int idx = tid + i * 256;
            const int row = idx >> 2, q = idx & 3;
            const uint32_t sm = (uint32_t)(row * GST + q * 4) * 4;
            const float* ga = A + (size_t)(bm + row) * GK + kc * 16 + q * 4;
            asm volatile("cp.async.cg.shared.global [%0], [%1], 16;" :: "r"(sa + sm), "l"(ga));
            const float* gb = B + (size_t)(bn + row) * GK + kc * 16 + q * 4;
            asm volatile("cp.async.cg.shared.global [%0], [%1], 16;" :: "r"(sb + sm), "l"(gb));
        }
        asm volatile("cp.async.commit_group;" ::: "memory");
    };

    issue(0); issue(1); issue(2);

    const int NKC = GK / 16;   // 64
    for (int kc = 0; kc < NKC; kc++) {
        if (kc < NKC - 2)      asm volatile("cp.async.wait_group 2;" ::: "memory");
        else if (kc == NKC - 2) asm volatile("cp.async.wait_group 1;" ::: "memory");
        else                   asm volatile("cp.async.wait_group 0;" ::: "memory");
        __syncthreads();
        if (kc + 3 < NKC) issue(kc + 3);

        const int st = kc & 3;
        const uint32_t sa = smb + (uint32_t)st * STAGE_FL * 4;
        const uint32_t sb = sa + STG_FL * 4;
#pragma unroll
        for (int ks = 0; ks < 2; ks++) {
            uint32_t af[4][4], bf[4][2];
#pragma unroll
            for (int im = 0; im < 4; im++)
                ldsm4(af[im][0], af[im][1], af[im][2], af[im][3],
                      sa + aB0 + (uint32_t)(im * 16 * GST * 4) + (uint32_t)(ks * 32));
#pragma unroll
            for (int inp = 0; inp < 2; inp++)
                ldsm4(bf[2 * inp][0], bf[2 * inp][1], bf[2 * inp + 1][0], bf[2 * inp + 1][1],
                      sb + bB0 + (uint32_t)(inp * 16 * GST * 4) + (uint32_t)(ks * 32));
#pragma unroll
            for (int im = 0; im < 4; im++)
#pragma unroll
                for (int in_ = 0; in_ < 4; in_++)
                    mma_tf32(acc[im][in_], af[im], bf[in_][0], bf[in_][1]);
        }
    }

    const bool kvt = (C2 != nullptr) && (bn >= c2_col0);
#pragma unroll
    for (int im = 0; im < 4; im++) {
        const int row0 = bm + wm + im * 16 + g;
#pragma unroll
        for (int in_ = 0; in_ < 4; in_++) {
            const int col = bn + wn + in_ * 8 + 2 * tg;
            float2 v0 = make_float2(acc[im][in_][0], acc[im][in_][1]);
            float2 v1 = make_float2(acc[im][in_][2], acc[im][in_][3]);
            *reinterpret_cast<float2*>(C + (size_t)row0 * N + col) = v0;
            *reinterpret_cast<float2*>(C + (size_t)(row0 + 8) * N + col) = v1;
            if (kvt) {
                const int c2c = col - c2_col0;
                *reinterpret_cast<float2*>(C2 + (size_t)row0 * c2_ld + c2c) = v0;
                *reinterpret_cast<float2*>(C2 + (size_t)(row0 + 8) * c2_ld + c2c) = v1;
            }
        }
    }
}

// ============================================================================
// Flash attention, mma.sync tf32, LDSM K fragments, smem P relayout,
// per-warp chunk skipping. Output stored pre-rounded to tf32.
// ============================================================================
#define KS_ST 68
#define VS_ST 72
#define PS_ST 68
#define KS_FL (64 * KS_ST)          // 4352
#define VS_FL (64 * VS_ST)          // 4608
#define P_FL  (16 * PS_ST)          // 1088 per warp
#define ATT_SMEM ((2 * KS_FL + 2 * VS_FL + 8 * P_FL) * 4)   // 106496 bytes

__global__ void __launch_bounds__(256, 2) attn_mma_kernel(
    const float* __restrict__ qkv, float* __restrict__ att)
{
    extern __shared__ float sm[];
    const int qt = blockIdx.x, h = blockIdx.y, n = blockIdx.z, hk = h >> 2;
    const int tid = threadIdx.x, wid = tid >> 5, lane = tid & 31;
    const int g = lane >> 2, tg = lane & 3;
    const int lr = lane & 7, lm = lane >> 3;
    const int abase = qt * 128 + wid * 16;
    const int a0 = abase + g, a1 = a0 + 8;
    const float qscale = 0.125f * 1.44269504f;
    const float slope2 = exp2f(-0.5f * (float)(h + 1)) * 1.44269504f;
    const uint32_t smb = smem_u32(sm);
    const bool nz = (n > 0);

    // per-warp P tile base (bytes)
    const uint32_t pbase = smb + (uint32_t)(2 * KS_FL + 2 * VS_FL + wid * P_FL) * 4;
    // LDSM base offsets
    const uint32_t kB0 = (uint32_t)((((lm >> 1) * 8 + lr) * KS_ST + (lm & 1) * 4) * 4); // B-op (K)
    const uint32_t pB0 = (uint32_t)((((lm & 1) * 8 + lr) * PS_ST + (lm >> 1) * 4) * 4); // A-op (P)

    // chunk-skip bounds
    const int jlo = (wid * 16 + 15 + 63) >> 6;
    const int jhi = (wid * 16 + 449) >> 6;

    // Q fragments (scale folded), persistent
    uint32_t qf[8][4];
    {
        const float* q0 = qkv + (size_t)(n * WIN + a0) * QKV_N + h * HD;
        const float* q1 = qkv + (size_t)(n * WIN + a1) * QKV_N + h * HD;
#pragma unroll
        for (int kc = 0; kc < 8; kc++) {
            qf[kc][0] = f2tf32(q0[kc * 8 + tg] * qscale);
            qf[kc][1] = f2tf32(q1[kc * 8 + tg] * qscale);
            qf[kc][2] = f2tf32(q0[kc * 8 + tg + 4] * qscale);
            qf[kc][3] = f2tf32(q1[kc * 8 + tg + 4] * qscale);
        }
    }

    float o[8][4];
#pragma unroll
    for (int i = 0; i < 8; i++)
#pragma unroll
        for (int j = 0; j < 4; j++) o[i][j] = 0.0f;
    float m0 = -1e30f, m1 = -1e30f, l0 = 0.0f, l1 = 0.0f;

    auto issue = [&](int ci) {
        const int st = ci & 1;
        const uint32_t kbase = smb + (uint32_t)st * KS_FL * 4;
        const uint32_t vbase = smb + (uint32_t)(2 * KS_FL + st * VS_FL) * 4;
        const int u0 = ci * 64;
#pragma unroll
        for (int i = 0; i < 4; i++) {
            const int idx = tid + i * 256;
            const int r = idx >> 4, c4 = idx & 15;
            const int gk = (n - 1) * WIN + u0 + r;
            const int pr = (gk >= 0) ? 16 : 0;
            const size_t base = (size_t)(gk >= 0 ? gk : 0) * QKV_N;
            const float* ks = qkv + base + (HQ + hk) * HD + c4 * 4;
            const float* vs = qkv + base + (HQ + HK + hk) * HD + c4 * 4;
            const uint32_t kd = kbase + (uint32_t)(r * KS_ST + c4 * 4) * 4;
            const uint32_t vd = vbase + (uint32_t)(r * VS_ST + c4 * 4) * 4;
            asm volatile("cp.async.cg.shared.global [%0], [%1], 16, %2;" :: "r"(kd), "l"(ks), "r"(pr));
            asm volatile("cp.async.cg.shared.global [%0], [%1], 16, %2;" :: "r"(vd), "l"(vs), "r"(pr));
        }
        asm volatile("cp.async.commit_group;" ::: "memory");
    };

    const int c0 = qt * 2;
    issue(c0);
    issue(c0 + 1);

    for (int ci = c0; ci < c0 + 10; ci++) {
        const int st = ci & 1;
        if (ci == c0 + 9) asm volatile("cp.async.wait_group 0;" ::: "memory");
        else              asm volatile("cp.async.wait_group 1;" ::: "memory");
        __syncthreads();

        const int j = ci - c0;
        const bool skip = ((wid >= 4) && (j == 0)) || ((wid < 4) && (j == 9)) ||
                          (!nz && (j <= 7 - 2 * qt));
        if (!skip) {
            const uint32_t kstb = smb + (uint32_t)st * KS_FL * 4;
            const float* Vst = sm + 2 * KS_FL + st * VS_FL;
            const int u0 = ci * 64;
            const bool needmask = (j < jlo) || (j > jhi) || (!nz && (j < 8 - 2 * qt));

            // ---- S = Q K^T via LDSM B fragments
            float sacc[8][4];
#pragma unroll
            for (int nt = 0; nt < 8; nt++)
#pragma unroll
                for (int jj = 0; jj < 4; jj++) sacc[nt][jj] = 0.0f;

#pragma unroll
            for (int ntp = 0; ntp < 4; ntp++) {
#pragma unroll
                for (int kc = 0; kc < 8; kc++) {
                    uint32_t b00, b01, b10, b11;
                    ldsm4(b00, b01, b10, b11,
                          kstb + kB0 + (uint32_t)(ntp * 16 * KS_ST * 4) + (uint32_t)(kc * 32));
                    mma_tf32(sacc[2 * ntp], qf[kc], b00, b01);
                    mma_tf32(sacc[2 * ntp + 1], qf[kc], b10, b11);
                }
            }

            // ---- mask/bias + row max
            float mx0 = -1e30f, mx1 = -1e30f;
            if (needmask) {
#pragma unroll
                for (int nt = 0; nt < 8; nt++) {
                    const int ub = u0 + nt * 8 + 2 * tg;
#pragma unroll
                    for (int jj = 0; jj < 4; jj++) {
                        const int u = ub + (jj & 1);
                        const int a = (jj < 2) ? a0 : a1;
                        const int diff = a + WIN - u;
                        const bool ok = ((unsigned)diff <= (unsigned)WIN) && (nz || (u >= WIN));
                        float s = ok ? (sacc[nt][jj] + slope2 * (float)u) : -1e30f;
                        sacc[nt][jj] = s;
                        if (jj < 2) mx0 = fmaxf(mx0, s);
                        else        mx1 = fmaxf(mx1, s);
                    }
                }
            } else {
#pragma unroll
                for (int nt = 0; nt < 8; nt++) {
                    const int ub = u0 + nt * 8 + 2 * tg;
#pragma unroll
                    for (int jj = 0; jj < 4; jj++) {
                        const int u = ub + (jj & 1);
                        float s = sacc[nt][jj] + slope2 * (float)u;
                        sacc[nt][jj] = s;
                        if (jj < 2) mx0 = fmaxf(mx0, s);
                        else        mx1 = fmaxf(mx1, s);
                    }
                }
            }
            mx0 = fmaxf(mx0, __shfl_xor_sync(FULLM, mx0, 1));
            mx0 = fmaxf(mx0, __shfl_xor_sync(FULLM, mx0, 2));
            mx1 = fmaxf(mx1, __shfl_xor_sync(FULLM, mx1, 1));
            mx1 = fmaxf(mx1, __shfl_xor_sync(FULLM, mx1, 2));

            const float nm0 = fmaxf(m0, mx0), nm1 = fmaxf(m1, mx1);
            const float cr0 = ex2f(m0 - nm0), cr1 = ex2f(m1 - nm1);
            l0 *= cr0; l1 *= cr1; m0 = nm0; m1 = nm1;
#pragma unroll
            for (int nt = 0; nt < 8; nt++) {
                o[nt][0] *= cr0; o[nt][1] *= cr0;
                o[nt][2] *= cr1; o[nt][3] *= cr1;
            }

            // ---- p = exp2(s - m), store rounded P to per-warp smem
#pragma unroll
            for (int nt = 0; nt < 8; nt++) {
                float p0 = ex2f(sacc[nt][0] - nm0);
                float p1 = ex2f(sacc[nt][1] - nm0);
                float p2 = ex2f(sacc[nt][2] - nm1);
                float p3 = ex2f(sacc[nt][3] - nm1);
                if (needmask) {
                    p0 = (sacc[nt][0] < -5e29f) ? 0.0f : p0;
                    p1 = (sacc[nt][1] < -5e29f) ? 0.0f : p1;
                    p2 = (sacc[nt][2] < -5e29f) ? 0.0f : p2;
                    p3 = (sacc[nt][3] < -5e29f) ? 0.0f : p3;
                }
                l0 += p0 + p1; l1 += p2 + p3;
                const uint32_t col = (uint32_t)(nt * 8 + 2 * tg);
                uint32_t r0 = f2tf32(p0), r1 = f2tf32(p1), r2 = f2tf32(p2), r3 = f2tf32(p3);
                asm volatile("st.shared.v2.b32 [%0], {%1, %2};"
                             :: "r"(pbase + (g * PS_ST + col) * 4), "r"(r0), "r"(r1));
                asm volatile("st.shared.v2.b32 [%0], {%1, %2};"
                             :: "r"(pbase + ((g + 8) * PS_ST + col) * 4), "r"(r2), "r"(r3));
            }
            __syncwarp();

            // ---- O += P V  (P A-frags via LDSM; V scalar LDS)
#pragma unroll
            for (int kc = 0; kc < 8; kc++) {
                uint32_t pa[4];
                ldsm4(pa[0], pa[1], pa[2], pa[3], pbase + pB0 + (uint32_t)(kc * 32));
                const float* vr0 = Vst + (kc * 8 + tg) * VS_ST;
                const float* vr1 = Vst + (kc * 8 + tg + 4) * VS_ST;
#pragma unroll
                for (int ntd = 0; ntd < 8; ntd++) {
                    uint32_t b0 = __float_as_uint(vr0[ntd * 8 + g]);
                    uint32_t b1 = __float_as_uint(vr1[ntd * 8 + g]);
                    mma_tf32(o[ntd], pa, b0, b1);
                }
            }
            __syncwarp();
        }

        __syncthreads();
        if (ci + 2 < c0 + 10) issue(ci + 2);
    }

    // ---- finalize
    l0 += __shfl_xor_sync(FULLM, l0, 1);
    l0 += __shfl_xor_sync(FULLM, l0, 2);
    l1 += __shfl_xor_sync(FULLM, l1, 1);
    l1 += __shfl_xor_sync(FULLM, l1, 2);
    const float i0 = 1.0f / l0, i1 = 1.0f / l1;

    float* o0 = att + (size_t)(n * WIN + a0) * D_MODEL + h * HD;
    float* o1 = att + (size_t)(n * WIN + a1) * D_MODEL + h * HD;
#pragma unroll
    for (int ntd = 0; ntd < 8; ntd++) {
        const int d = ntd * 8 + 2 * tg;
        float2 v0, v1;
        v0.x = __uint_as_float(f2tf32(o[ntd][0] * i0));
        v0.y = __uint_as_float(f2tf32(o[ntd][1] * i0));
        v1.x = __uint_as_float(f2tf32(o[ntd][2] * i1));
        v1.y = __uint_as_float(f2tf32(o[ntd][3] * i1));
        *reinterpret_cast<float2*>(o0 + d) = v0;
        *reinterpret_cast<float2*>(o1 + d) = v1;
    }
}

// ============================================================================
// Host launcher
// ============================================================================
extern "C" void kernel_launch(void* const* d_in, const int* in_sizes, int n_in,
                              void* d_out, int out_size)
{
    const float* x     = (const float*)d_in[0];
    const float* Wqkv  = (const float*)d_in[1];
    const float* Wproj = (const float*)d_in[2];

    float* out = (float*)d_out;
    float* kv  = out + (size_t)S_LEN * D_MODEL;

    float *qkv = nullptr, *att = nullptr, *xr = nullptr, *wqkvr = nullptr, *wprojr = nullptr;
    cudaGetSymbolAddress((void**)&qkv, g_qkv);
    cudaGetSymbolAddress((void**)&att, g_att);
    cudaGetSymbolAddress((void**)&xr, g_xr);
    cudaGetSymbolAddress((void**)&wqkvr, g_wqkvr);
    cudaGetSymbolAddress((void**)&wprojr, g_wprojr);

    cudaFuncSetAttribute(gemm_mma_kernel,
                         cudaFuncAttributeMaxDynamicSharedMemorySize, GEMM_SMEM);
    cudaFuncSetAttribute(attn_mma_kernel,
                         cudaFuncAttributeMaxDynamicSharedMemorySize, ATT_SMEM);

    // 0) pre-round inputs to tf32
    round_kernel<<<1024, 256>>>(x, xr, (S_LEN * D_MODEL) / 4);
    round_kernel<<<512, 256>>>(Wqkv, wqkvr, (QKV_N * D_MODEL) / 4);
    round_kernel<<<512, 256>>>(Wproj, wprojr, (D_MODEL * D_MODEL) / 4);

    // 1) QKV GEMM: [8192,1536]; kv_cache slice fused
    gemm_mma_kernel<<<dim3(QKV_N / 128, S_LEN / 128), 256, GEMM_SMEM>>>(
        xr, wqkvr, qkv, kv, QKV_N, KV_COL0, KV_LD);

    // 2) sliding-window attention -> att [8192, 1024] (stored tf32-rounded)
    attn_mma_kernel<<<dim3(4, HQ, NB), 256, ATT_SMEM>>>(qkv, att);

    // 3) projection GEMM: out = att @ Wproj^T
    gemm_mma_kernel<<<dim3(D_MODEL / 128, S_LEN / 128), 256, GEMM_SMEM>>>(
        att, wprojr, out, nullptr, D_MODEL, 0, 0);
}

// round 8
// speedup vs baseline: 4.5587x; 1.1065x over previous
#include <cuda_runtime.h>
#include <cuda_bf16.h>
#include <cstdint>

// Problem constants (B=1, S=8192, D=1024, Hq=16, Hk=4, hd=64, W=512)
#define S_LEN   8192
#define D_MODEL 1024
#define QKV_N   1536
#define HQ      16
#define HK      4
#define HD      64
#define WIN     512
#define NB      16
#define KV_COL0 1024
#define KV_LD   512
#define GK      1024
#define FULLM   0xffffffffu

__device__ float g_qkv[(size_t)S_LEN * QKV_N];
__device__ float g_att[(size_t)S_LEN * D_MODEL];
__device__ float g_xr[(size_t)S_LEN * D_MODEL];
__device__ float g_wqkvr[(size_t)QKV_N * D_MODEL];
__device__ float g_wprojr[(size_t)D_MODEL * D_MODEL];

__device__ __forceinline__ uint32_t smem_u32(const void* p) {
    uint32_t a;
    asm("{ .reg .u64 t; cvta.to.shared.u64 t, %1; cvt.u32.u64 %0, t; }" : "=r"(a) : "l"(p));
    return a;
}
__device__ __forceinline__ uint32_t f2tf32(float x) {
    uint32_t u;
    asm("cvt.rna.tf32.f32 %0, %1;" : "=r"(u) : "f"(x));
    return u;
}
__device__ __forceinline__ float ex2f(float x) {
    float y;
    asm("ex2.approx.f32 %0, %1;" : "=f"(y) : "f"(x));
    return y;
}
__device__ __forceinline__ void mma_tf32(float c[4], const uint32_t a[4], uint32_t b0, uint32_t b1) {
    asm volatile(
        "mma.sync.aligned.m16n8k8.row.col.f32.tf32.tf32.f32 "
        "{%0,%1,%2,%3}, {%4,%5,%6,%7}, {%8,%9}, {%0,%1,%2,%3};"
        : "+f"(c[0]), "+f"(c[1]), "+f"(c[2]), "+f"(c[3])
        : "r"(a[0]), "r"(a[1]), "r"(a[2]), "r"(a[3]), "r"(b0), "r"(b1));
}
__device__ __forceinline__ void ldsm4(uint32_t& r0, uint32_t& r1, uint32_t& r2, uint32_t& r3, uint32_t a) {
    asm volatile("ldmatrix.sync.aligned.m8n8.x4.shared.b16 {%0,%1,%2,%3}, [%4];"
        : "=r"(r0), "=r"(r1), "=r"(r2), "=r"(r3) : "r"(a));
}

// ============================================================================
// Pre-round to tf32 (rna), elementwise, float4 granularity.
// ============================================================================
__global__ void __launch_bounds__(256) round_kernel(
    const float* __restrict__ src, float* __restrict__ dst, int n4)
{
    int i = blockIdx.x * blockDim.x + threadIdx.x;
    int stride = gridDim.x * blockDim.x;
    for (; i < n4; i += stride) {
        float4 v = reinterpret_cast<const float4*>(src)[i];
        v.x = __uint_as_float(f2tf32(v.x));
        v.y = __uint_as_float(f2tf32(v.y));
        v.z = __uint_as_float(f2tf32(v.z));
        v.w = __uint_as_float(f2tf32(v.w));
        reinterpret_cast<float4*>(dst)[i] = v;
    }
}

// ============================================================================
// tf32 mma.sync GEMM: CTA 128x128, 512 threads (16 warps, 4x4), warp 32x32.
// 3-stage cp.async pipeline, ldmatrix fragments. Inputs pre-rounded to tf32.
// ============================================================================
#define GST 20                      // smem row stride (floats) — LDSM conflict-free
#define STG_FL (128 * GST)          // 2560 floats per tensor per stage
#define STAGE_FL (2 * STG_FL)       // 5120
#define GEMM_SMEM (3 * STAGE_FL * 4)  // 61440 bytes

__global__ void __launch_bounds__(512, 2) gemm_mma_kernel(
    const float* __restrict__ A, const float* __restrict__ B,
    float* __restrict__ C, float* __restrict__ C2,
    int N, int c2_col0, int c2_ld)
{
    extern __shared__ float gsm[];
    const uint32_t smb = smem_u32(gsm);

    const int tid = threadIdx.x;
    const int wid = tid >> 5, lane = tid & 31;
    const int g = lane >> 2, tg = lane & 3;
    const int lr = lane & 7, lm = lane >> 3;
    const int wm = (wid & 3) * 32;
    const int wn = (wid >> 2) * 32;
    const int bm = blockIdx.y * 128, bn = blockIdx.x * 128;

    const uint32_t aB0 = (uint32_t)(((wm + (lm & 1) * 8 + lr) * GST + (lm >> 1) * 4) * 4);
    const uint32_t bB0 = (uint32_t)(((wn + (lm >> 1) * 8 + lr) * GST + (lm & 1) * 4) * 4);

    float acc[2][4][4];
#pragma unroll
    for (int i = 0; i < 2; i++)
#pragma unroll
        for (int j = 0; j < 4; j++)
#pragma unroll
            for (int r = 0; r < 4; r++) acc[i][j][r] = 0.0f;

    auto issue = [&](int kc) {
        const int st = kc % 3;
        const uint32_t sa = smb + (uint32_t)st * STAGE_FL * 4;
        const uint32_t sb = sa + STG_FL * 4;
        const int row = tid >> 2, q = tid & 3;
        const uint32_t sm = (uint32_t)(row * GST + q * 4) * 4;
        const float* ga = A + (size_t)(bm + row) * GK + kc * 16 + q * 4;
        asm volatile("cp.async.cg.shared.global [%0], [%1], 16;" :: "r"(sa + sm), "l"(ga));
        const float* gb = B + (size_t)(bn + row) * GK + kc * 16 + q * 4;
        asm volatile("cp.async.cg.shared.global [%0], [%1], 16;" :: "r"(sb + sm), "l"(gb));
        asm volatile("cp.async.commit_group;" ::: "memory");
    };

    issue(0); issue(1);

    const int NKC = GK / 16;   // 64
    for (int kc = 0; kc < NKC; kc++) {
        if (kc < NKC - 1) asm volatile("cp.async.wait_group 1;" ::: "memory");
        else              asm volatile("cp.async.wait_group 0;" ::: "memory");
        __syncthreads();
        if (kc + 2 < NKC) issue(kc + 2);

        const int st = kc % 3;
        const uint32_t sa = smb + (uint32_t)st * STAGE_FL * 4;
        const uint32_t sb = sa + STG_FL * 4;
#pragma unroll
        for (int ks = 0; ks < 2; ks++) {
            uint32_t af[2][4], bf[4][2];
#pragma unroll
            for (int im = 0; im < 2; im++)
                ldsm4(af[im][0], af[im][1], af[im][2], af[im][3],
                      sa + aB0 + (uint32_t)(im * 16 * GST * 4) + (uint32_t)(ks * 32));
#pragma unroll
            for (int inp = 0; inp < 2; inp++)
                ldsm4(bf[2 * inp][0], bf[2 * inp][1], bf[2 * inp + 1][0], bf[2 * inp + 1][1],
                      sb + bB0 + (uint32_t)(inp * 16 * GST * 4) + (uint32_t)(ks * 32));
#pragma unroll
            for (int im = 0; im < 2; im++)
#pragma unroll
                for (int in_ = 0; in_ < 4; in_++)
                    mma_tf32(acc[im][in_], af[im], bf[in_][0], bf[in_][1]);
        }
    }

    const bool kvt = (C2 != nullptr) && (bn >= c2_col0);
#pragma unroll
    for (int im = 0; im < 2; im++) {
        const int row0 = bm + wm + im * 16 + g;
#pragma unroll
        for (int in_ = 0; in_ < 4; in_++) {
            const int col = bn + wn + in_ * 8 + 2 * tg;
            float2 v0 = make_float2(acc[im][in_][0], acc[im][in_][1]);
            float2 v1 = make_float2(acc[im][in_][2], acc[im][in_][3]);
            *reinterpret_cast<float2*>(C + (size_t)row0 * N + col) = v0;
            *reinterpret_cast<float2*>(C + (size_t)(row0 + 8) * N + col) = v1;
            if (kvt) {
                const int c2c = col - c2_col0;
                *reinterpret_cast<float2*>(C2 + (size_t)row0 * c2_ld + c2c) = v0;
                *reinterpret_cast<float2*>(C2 + (size_t)(row0 + 8) * c2_ld + c2c) = v1;
            }
        }
    }
}

// ============================================================================
// Flash attention, mma.sync tf32, LDSM K fragments, smem P relayout,
// per-warp chunk skipping. Output stored pre-rounded to tf32.
// ============================================================================
#define KS_ST 68
#define VS_ST 72
#define PS_ST 68
#define KS_FL (64 * KS_ST)
#define VS_FL (64 * VS_ST)
#define P_FL  (16 * PS_ST)
#define ATT_SMEM ((2 * KS_FL + 2 * VS_FL + 8 * P_FL) * 4)   // 106496 bytes

__global__ void __launch_bounds__(256, 2) attn_mma_kernel(
    const float* __restrict__ qkv, float* __restrict__ att)
{
    extern __shared__ float sm[];
    const int qt = blockIdx.x, h = blockIdx.y, n = blockIdx.z, hk = h >> 2;
    const int tid = threadIdx.x, wid = tid >> 5, lane = tid & 31;
    const int g = lane >> 2, tg = lane & 3;
    const int lr = lane & 7, lm = lane >> 3;
    const int abase = qt * 128 + wid * 16;
    const int a0 = abase + g, a1 = a0 + 8;
    const float qscale = 0.125f * 1.44269504f;
    const float slope2 = exp2f(-0.5f * (float)(h + 1)) * 1.44269504f;
    const uint32_t smb = smem_u32(sm);
    const bool nz = (n > 0);

    const uint32_t pbase = smb + (uint32_t)(2 * KS_FL + 2 * VS_FL + wid * P_FL) * 4;
    const uint32_t kB0 = (uint32_t)((((lm >> 1) * 8 + lr) * KS_ST + (lm & 1) * 4) * 4);
    const uint32_t pB0 = (uint32_t)((((lm & 1) * 8 + lr) * PS_ST + (lm >> 1) * 4) * 4);

    const int jlo = (wid * 16 + 15 + 63) >> 6;
    const int jhi = (wid * 16 + 449) >> 6;

    uint32_t qf[8][4];
    {
        const float* q0 = qkv + (size_t)(n * WIN + a0) * QKV_N + h * HD;
        const float* q1 = qkv + (size_t)(n * WIN + a1) * QKV_N + h * HD;
#pragma unroll
        for (int kc = 0; kc < 8; kc++) {
            qf[kc][0] = f2tf32(q0[kc * 8 + tg] * qscale);
            qf[kc][1] = f2tf32(q1[kc * 8 + tg] * qscale);
            qf[kc][2] = f2tf32(q0[kc * 8 + tg + 4] * qscale);
            qf[kc][3] = f2tf32(q1[kc * 8 + tg + 4] * qscale);
        }
    }

    float o[8][4];
#pragma unroll
    for (int i = 0; i < 8; i++)
#pragma unroll
        for (int j = 0; j < 4; j++) o[i][j] = 0.0f;
    float m0 = -1e30f, m1 = -1e30f, l0 = 0.0f, l1 = 0.0f;

    auto issue = [&](int ci) {
        const int st = ci & 1;
        const uint32_t kbase = smb + (uint32_t)st * KS_FL * 4;
        const uint32_t vbase = smb + (uint32_t)(2 * KS_FL + st * VS_FL) * 4;
        const int u0 = ci * 64;
#pragma unroll
        for (int i = 0; i < 4; i++) {
            const int idx = tid + i * 256;
            const int r = idx >> 4, c4 = idx & 15;
            const int gk = (n - 1) * WIN + u0 + r;
            const int pr = (gk >= 0) ? 16 : 0;
            const size_t base = (size_t)(gk >= 0 ? gk : 0) * QKV_N;
            const float* ks = qkv + base + (HQ + hk) * HD + c4 * 4;
            const float* vs = qkv + base + (HQ + HK + hk) * HD + c4 * 4;
            const uint32_t kd = kbase + (uint32_t)(r * KS_ST + c4 * 4) * 4;
            const uint32_t vd = vbase + (uint32_t)(r * VS_ST + c4 * 4) * 4;
            asm volatile("cp.async.cg.shared.global [%0], [%1], 16, %2;" :: "r"(kd), "l"(ks), "r"(pr));
            asm volatile("cp.async.cg.shared.global [%0], [%1], 16, %2;" :: "r"(vd), "l"(vs), "r"(pr));
        }
        asm volatile("cp.async.commit_group;" ::: "memory");
    };

    const int c0 = qt * 2;
    issue(c0);
    issue(c0 + 1);

    for (int ci = c0; ci < c0 + 10; ci++) {
        const int st = ci & 1;
        if (ci == c0 + 9) asm volatile("cp.async.wait_group 0;" ::: "memory");
        else              asm volatile("cp.async.wait_group 1;" ::: "memory");
        __syncthreads();

        const int j = ci - c0;
        const bool skip = ((wid >= 4) && (j == 0)) || ((wid < 4) && (j == 9)) ||
                          (!nz && (j <= 7 - 2 * qt));
        if (!skip) {
            const uint32_t kstb = smb + (uint32_t)st * KS_FL * 4;
            const float* Vst = sm + 2 * KS_FL + st * VS_FL;
            const int u0 = ci * 64;
            const bool needmask = (j < jlo) || (j > jhi) || (!nz && (j < 8 - 2 * qt));

            float sacc[8][4];
#pragma unroll
            for (int nt = 0; nt < 8; nt++)
#pragma unroll
                for (int jj = 0; jj < 4; jj++) sacc[nt][jj] = 0.0f;

#pragma unroll
            for (int ntp = 0; ntp < 4; ntp++) {
#pragma unroll
                for (int kc = 0; kc < 8; kc++) {
                    uint32_t b00, b01, b10, b11;
                    ldsm4(b00, b01, b10, b11,
                          kstb + kB0 + (uint32_t)(ntp * 16 * KS_ST * 4) + (uint32_t)(kc * 32));
                    mma_tf32(sacc[2 * ntp], qf[kc], b00, b01);
                    mma_tf32(sacc[2 * ntp + 1], qf[kc], b10, b11);
                }
            }

            float mx0 = -1e30f, mx1 = -1e30f;
            if (needmask) {
#pragma unroll
                for (int nt = 0; nt < 8; nt++) {
                    const int ub = u0 + nt * 8 + 2 * tg;
#pragma unroll
                    for (int jj = 0; jj < 4; jj++) {
                        const int u = ub + (jj & 1);
                        const int a = (jj < 2) ? a0 : a1;
                        const int diff = a + WIN - u;
                        const bool ok = ((unsigned)diff <= (unsigned)WIN) && (nz || (u >= WIN));
                        float s = ok ? (sacc[nt][jj] + slope2 * (float)u) : -1e30f;
                        sacc[nt][jj] = s;
                        if (jj < 2) mx0 = fmaxf(mx0, s);
                        else        mx1 = fmaxf(mx1, s);
                    }
                }
            } else {
#pragma unroll
                for (int nt = 0; nt < 8; nt++) {
                    const int ub = u0 + nt * 8 + 2 * tg;
#pragma unroll
                    for (int jj = 0; jj < 4; jj++) {
                        const int u = ub + (jj & 1);
                        float s = sacc[nt][jj] + slope2 * (float)u;
                        sacc[nt][jj] = s;
                        if (jj < 2) mx0 = fmaxf(mx0, s);
                        else        mx1 = fmaxf(mx1, s);
                    }
                }
            }
            mx0 = fmaxf(mx0, __shfl_xor_sync(FULLM, mx0, 1));
            mx0 = fmaxf(mx0, __shfl_xor_sync(FULLM, mx0, 2));
            mx1 = fmaxf(mx1, __shfl_xor_sync(FULLM, mx1, 1));
            mx1 = fmaxf(mx1, __shfl_xor_sync(FULLM, mx1, 2));

            const float nm0 = fmaxf(m0, mx0), nm1 = fmaxf(m1, mx1);
            const float cr0 = ex2f(m0 - nm0), cr1 = ex2f(m1 - nm1);
            l0 *= cr0; l1 *= cr1; m0 = nm0; m1 = nm1;
#pragma unroll
            for (int nt = 0; nt < 8; nt++) {
                o[nt][0] *= cr0; o[nt][1] *= cr0;
                o[nt][2] *= cr1; o[nt][3] *= cr1;
            }

#pragma unroll
            for (int nt = 0; nt < 8; nt++) {
                float p0 = ex2f(sacc[nt][0] - nm0);
                float p1 = ex2f(sacc[nt][1] - nm0);
                float p2 = ex2f(sacc[nt][2] - nm1);
                float p3 = ex2f(sacc[nt][3] - nm1);
                if (needmask) {
                    p0 = (sacc[nt][0] < -5e29f) ? 0.0f : p0;
                    p1 = (sacc[nt][1] < -5e29f) ? 0.0f : p1;
                    p2 = (sacc[nt][2] < -5e29f) ? 0.0f : p2;
                    p3 = (sacc[nt][3] < -5e29f) ? 0.0f : p3;
                }
                l0 += p0 + p1; l1 += p2 + p3;
                const uint32_t col = (uint32_t)(nt * 8 + 2 * tg);
                uint32_t r0 = f2tf32(p0), r1 = f2tf32(p1), r2 = f2tf32(p2), r3 = f2tf32(p3);
                asm volatile("st.shared.v2.b32 [%0], {%1, %2};"
                             :: "r"(pbase + (g * PS_ST + col) * 4), "r"(r0), "r"(r1));
                asm volatile("st.shared.v2.b32 [%0], {%1, %2};"
                             :: "r"(pbase + ((g + 8) * PS_ST + col) * 4), "r"(r2), "r"(r3));
            }
            __syncwarp();

#pragma unroll
            for (int kc = 0; kc < 8; kc++) {
                uint32_t pa[4];
                ldsm4(pa[0], pa[1], pa[2], pa[3], pbase + pB0 + (uint32_t)(kc * 32));
                const float* vr0 = Vst + (kc * 8 + tg) * VS_ST;
                const float* vr1 = Vst + (kc * 8 + tg + 4) * VS_ST;
#pragma unroll
                for (int ntd = 0; ntd < 8; ntd++) {
                    uint32_t b0 = __float_as_uint(vr0[ntd * 8 + g]);
                    uint32_t b1 = __float_as_uint(vr1[ntd * 8 + g]);
                    mma_tf32(o[ntd], pa, b0, b1);
                }
            }
            __syncwarp();
        }

        __syncthreads();
        if (ci + 2 < c0 + 10) issue(ci + 2);
    }

    l0 += __shfl_xor_sync(FULLM, l0, 1);
    l0 += __shfl_xor_sync(FULLM, l0, 2);
    l1 += __shfl_xor_sync(FULLM, l1, 1);
    l1 += __shfl_xor_sync(FULLM, l1, 2);
    const float i0 = 1.0f / l0, i1 = 1.0f / l1;

    float* o0 = att + (size_t)(n * WIN + a0) * D_MODEL + h * HD;
    float* o1 = att + (size_t)(n * WIN + a1) * D_MODEL + h * HD;
#pragma unroll
    for (int ntd = 0; ntd < 8; ntd++) {
        const int d = ntd * 8 + 2 * tg;
        float2 v0, v1;
        v0.x = __uint_as_float(f2tf32(o[ntd][0] * i0));
        v0.y = __uint_as_float(f2tf32(o[ntd][1] * i0));
        v1.x = __uint_as_float(f2tf32(o[ntd][2] * i1));
        v1.y = __uint_as_float(f2tf32(o[ntd][3] * i1));
        *reinterpret_cast<float2*>(o0 + d) = v0;
        *reinterpret_cast<float2*>(o1 + d) = v1;
    }
}

// ============================================================================
// Host launcher
// ============================================================================
extern "C" void kernel_launch(void* const* d_in, const int* in_sizes, int n_in,
                              void* d_out, int out_size)
{
    const float* x     = (const float*)d_in[0];
    const float* Wqkv  = (const float*)d_in[1];
    const float* Wproj = (const float*)d_in[2];

    float* out = (float*)d_out;
    float* kv  = out + (size_t)S_LEN * D_MODEL;

    float *qkv = nullptr, *att = nullptr, *xr = nullptr, *wqkvr = nullptr, *wprojr = nullptr;
    cudaGetSymbolAddress((void**)&qkv, g_qkv);
    cudaGetSymbolAddress((void**)&att, g_att);
    cudaGetSymbolAddress((void**)&xr, g_xr);
    cudaGetSymbolAddress((void**)&wqkvr, g_wqkvr);
    cudaGetSymbolAddress((void**)&wprojr, g_wprojr);

    cudaFuncSetAttribute(gemm_mma_kernel,
                         cudaFuncAttributeMaxDynamicSharedMemorySize, GEMM_SMEM);
    cudaFuncSetAttribute(attn_mma_kernel,
                         cudaFuncAttributeMaxDynamicSharedMemorySize, ATT_SMEM);

    // 0) pre-round inputs to tf32
    round_kernel<<<1024, 256>>>(x, xr, (S_LEN * D_MODEL) / 4);
    round_kernel<<<512, 256>>>(Wqkv, wqkvr, (QKV_N * D_MODEL) / 4);
    round_kernel<<<512, 256>>>(Wproj, wprojr, (D_MODEL * D_MODEL) / 4);

    // 1) QKV GEMM: [8192,1536]; kv_cache slice fused
    gemm_mma_kernel<<<dim3(QKV_N / 128, S_LEN / 128), 512, GEMM_SMEM>>>(
        xr, wqkvr, qkv, kv, QKV_N, KV_COL0, KV_LD);

    // 2) sliding-window attention -> att [8192, 1024] (stored tf32-rounded)
    attn_mma_kernel<<<dim3(4, HQ, NB), 256, ATT_SMEM>>>(qkv, att);

    // 3) projection GEMM: out = att @ Wproj^T
    gemm_mma_kernel<<<dim3(D_MODEL / 128, S_LEN / 128), 512, GEMM_SMEM>>>(
        att, wprojr, out, nullptr, D_MODEL, 0, 0);
}